// round 13
// baseline (speedup 1.0000x reference)
#include <cuda_runtime.h>
#include <math.h>

#define N_NODES 100000
#define N_EDGES 1600000
#define N_GRAPHS 512

// ---------------- device scratch (no cudaMalloc allowed) ----------------
__device__ __align__(256) float4 g_y1[N_NODES * 16];   // 64 ch fp32, PRE-SCALED by dinv[src]
__device__ __align__(256) float4 g_z1[N_NODES * 16];   // 64 ch fp32
__device__ __align__(256) float4 g_y2[N_NODES * 8];    // 32 ch fp32, pre-scaled
__device__ __align__(256) float4 g_z2[N_NODES * 8];    // 32 ch fp32
__device__ int      g_indeg[N_NODES];     // reset by k_scanC
__device__ int      g_rowptr[N_NODES + 1];
__device__ int      g_cursor[N_NODES];
__device__ int      g_col[N_EDGES];
__device__ float    g_dinv[N_NODES];
__device__ float    g_bns[96];            // reset by k_mlp
__device__ float    g_bnq[96];            // reset by k_mlp
__device__ float    g_psum[N_GRAPHS * 32];   // reset by k_mlp
__device__ unsigned g_pmax[N_GRAPHS * 32];   // reset by k_mlp
__device__ float    g_cnt[N_GRAPHS];         // reset by k_mlp
__device__ int      g_bsums[512];

__device__ __forceinline__ float elu(float x) {
    return x > 0.f ? x : (__expf(x) - 1.f);
}
__device__ __forceinline__ unsigned encf(float f) {
    unsigned u = __float_as_uint(f);
    return (u & 0x80000000u) ? ~u : (u | 0x80000000u);
}
__device__ __forceinline__ float decf(unsigned u) {
    return (u & 0x80000000u) ? __uint_as_float(u ^ 0x80000000u)
                             : __uint_as_float(~u);
}

// ---------------- CSR build ----------------
__global__ void k_deg(const int* __restrict__ ei) {
    int e = blockIdx.x * blockDim.x + threadIdx.x;
    if (e < N_EDGES) atomicAdd(&g_indeg[ei[N_EDGES + e]], 1);
}

__global__ void k_scanA() {
    __shared__ int wsum[8];
    int tid = threadIdx.x, lane = tid & 31, w = tid >> 5;
    int i = blockIdx.x * 256 + tid;
    int v = (i < N_NODES) ? g_indeg[i] : 0;
    int sc = v;
    #pragma unroll
    for (int o = 1; o < 32; o <<= 1) {
        int t = __shfl_up_sync(0xffffffffu, sc, o);
        if (lane >= o) sc += t;
    }
    if (lane == 31) wsum[w] = sc;
    __syncthreads();
    if (w == 0) {
        int ws = (lane < 8) ? wsum[lane] : 0;
        #pragma unroll
        for (int o = 1; o < 8; o <<= 1) {
            int t = __shfl_up_sync(0xffffffffu, ws, o);
            if (lane >= o) ws += t;
        }
        if (lane < 8) wsum[lane] = ws;
    }
    __syncthreads();
    int inc = sc + ((w > 0) ? wsum[w - 1] : 0);
    if (i < N_NODES) g_rowptr[i + 1] = inc;
    if (tid == 255) g_bsums[blockIdx.x] = inc;
}

__global__ void k_scanC() {
    __shared__ int red[8];
    __shared__ int s_off;
    int tid = threadIdx.x, lane = tid & 31, w = tid >> 5;
    int acc = 0;
    for (int t = tid; t < (int)blockIdx.x; t += 256) acc += g_bsums[t];
    #pragma unroll
    for (int o = 16; o; o >>= 1) acc += __shfl_down_sync(0xffffffffu, acc, o);
    if (lane == 0) red[w] = acc;
    __syncthreads();
    if (tid == 0) {
        int s = 0;
        #pragma unroll
        for (int k = 0; k < 8; k++) s += red[k];
        s_off = s;
    }
    __syncthreads();
    int i = blockIdx.x * 256 + tid;
    if (i < N_NODES) {
        int inc = g_rowptr[i + 1] + s_off;
        g_rowptr[i + 1] = inc;
        int dg = g_indeg[i];
        g_indeg[i] = 0;                       // self-clean
        g_cursor[i] = inc - dg;
        g_dinv[i] = rsqrtf((float)dg + 1.0f);
        if (i == 0) g_rowptr[0] = 0;
    }
}

__global__ void k_fill(const int* __restrict__ ei) {
    int e = blockIdx.x * blockDim.x + threadIdx.x;
    if (e < N_EDGES) {
        int s = ei[e];
        int d = ei[N_EDGES + e];
        int p = atomicAdd(&g_cursor[d], 1);
        g_col[p] = s;
    }
}

// ---------------- layer 1 ----------------
// y1 = (x @ W1) * dinv (fp32). k-vectorized smem (float2), conflict-free row spacing.
__global__ void k_gemm1(const float* __restrict__ x, const float* __restrict__ W1) {
    __shared__ float2 xs2[64][33];   // [row][k/2], row stride 66 words == 2 mod 32
    __shared__ float4 ws4[66][16];
    int tid = threadIdx.x;
    int row0 = blockIdx.x * 64;
    const float4* __restrict__ W14 = (const float4*)W1;
    for (int i = tid; i < 66 * 16; i += 256) ws4[i >> 4][i & 15] = W14[i];
    for (int i = tid; i < 64 * 33; i += 256) {
        int r = i / 33, kk = i - r * 33;
        int gr = row0 + r;
        float a = 0.f, b = 0.f;
        if (gr < N_NODES) {
            a = x[gr * 66 + 2 * kk];
            b = x[gr * 66 + 2 * kk + 1];
        }
        xs2[r][kk] = make_float2(a, b);
    }
    __syncthreads();
    int tx = tid & 15, ty = tid >> 4;
    float acc[4][4];
    #pragma unroll
    for (int i = 0; i < 4; i++)
        #pragma unroll
        for (int j = 0; j < 4; j++) acc[i][j] = 0.f;
    for (int kk = 0; kk < 33; kk++) {
        float4 w0 = ws4[2 * kk][tx];
        float4 w1 = ws4[2 * kk + 1][tx];
        #pragma unroll
        for (int i = 0; i < 4; i++) {
            float2 xv = xs2[ty + 16 * i][kk];
            acc[i][0] = fmaf(xv.x, w0.x, fmaf(xv.y, w1.x, acc[i][0]));
            acc[i][1] = fmaf(xv.x, w0.y, fmaf(xv.y, w1.y, acc[i][1]));
            acc[i][2] = fmaf(xv.x, w0.z, fmaf(xv.y, w1.z, acc[i][2]));
            acc[i][3] = fmaf(xv.x, w0.w, fmaf(xv.y, w1.w, acc[i][3]));
        }
    }
    #pragma unroll
    for (int i = 0; i < 4; i++) {
        int r = row0 + ty + 16 * i;
        if (r < N_NODES) {
            float d = g_dinv[r];
            g_y1[r * 16 + tx] = make_float4(acc[i][0] * d, acc[i][1] * d,
                                            acc[i][2] * d, acc[i][3] * d);
        }
    }
}

// layer-1 aggregation: TWO nodes/warp, 16 lanes x float4 (4ch each); fused BN stats
__global__ void __launch_bounds__(256, 6) k_agg64() {
    __shared__ float bs[64], bq[64];
    int tid = threadIdx.x;
    if (tid < 64) { bs[tid] = 0.f; bq[tid] = 0.f; }
    __syncthreads();
    int lane = tid & 31;
    int half = lane >> 4, hl = lane & 15;
    int warp = blockIdx.x * 8 + (tid >> 5);
    int nwarps = gridDim.x * 8;
    const float4* __restrict__ y = g_y1;
    float4* __restrict__ z = g_z1;
    float s0a = 0.f, s1a = 0.f, s2a = 0.f, s3a = 0.f;
    float q0a = 0.f, q1a = 0.f, q2a = 0.f, q3a = 0.f;
    for (int p = warp; p < N_NODES / 2; p += nwarps) {
        int n = 2 * p + half;
        int start = g_rowptr[n], end = g_rowptr[n + 1];
        int c = end - start;
        float dn = g_dinv[n];
        float4 a = y[n * 16 + hl];                       // self (pre-scaled)
        int cpeer = __shfl_xor_sync(0xffffffffu, c, 16); // convergent
        int cm = c > cpeer ? c : cpeer;
        for (int base = 0; base < cm; base += 16) {
            int m = c - base;
            if (m < 0) m = 0;
            if (m > 16) m = 16;
            int mm = cm - base;
            if (mm > 16) mm = 16;
            int s = (hl < m) ? g_col[start + base + hl] : 0;
            for (int j = 0; j < mm; j++) {
                int sj = __shfl_sync(0xffffffffu, s, j, 16);
                if (j < m) {
                    float4 v = y[sj * 16 + hl];
                    a.x += v.x; a.y += v.y; a.z += v.z; a.w += v.w;
                }
            }
        }
        a.x *= dn; a.y *= dn; a.z *= dn; a.w *= dn;
        z[n * 16 + hl] = a;
        s0a += a.x; q0a += a.x * a.x;
        s1a += a.y; q1a += a.y * a.y;
        s2a += a.z; q2a += a.z * a.z;
        s3a += a.w; q3a += a.w * a.w;
    }
    atomicAdd(&bs[4 * hl + 0], s0a); atomicAdd(&bq[4 * hl + 0], q0a);
    atomicAdd(&bs[4 * hl + 1], s1a); atomicAdd(&bq[4 * hl + 1], q1a);
    atomicAdd(&bs[4 * hl + 2], s2a); atomicAdd(&bq[4 * hl + 2], q2a);
    atomicAdd(&bs[4 * hl + 3], s3a); atomicAdd(&bq[4 * hl + 3], q3a);
    __syncthreads();
    if (tid < 64) { atomicAdd(&g_bns[tid], bs[tid]); atomicAdd(&g_bnq[tid], bq[tid]); }
}

// ---------------- layer 2 ----------------
// h1 = elu(BN(z1)); y2 = (h1 @ W2) * dinv. BN finalize fused; k-vectorized smem.
__global__ void k_gemm2(const float* __restrict__ W2,
                        const float* __restrict__ g1, const float* __restrict__ be1) {
    __shared__ float2 hs2[64][33];   // [row][k/2], stride 66 words == 2 mod 32
    __shared__ float4 ws4[64][8];
    __shared__ float  sc[64], sh[64];
    int tid = threadIdx.x;          // 128 threads
    int row0 = blockIdx.x * 64;
    if (tid < 64) {
        float m = g_bns[tid] * (1.0f / N_NODES);
        float var = g_bnq[tid] * (1.0f / N_NODES) - m * m;
        float r = rsqrtf(var + 1e-5f);
        float s = g1[tid] * r;
        sc[tid] = s;
        sh[tid] = be1[tid] - m * s;
    }
    const float4* __restrict__ W24 = (const float4*)W2;
    for (int i = tid; i < 64 * 8; i += 128) ws4[i >> 3][i & 7] = W24[i];
    __syncthreads();
    const float* __restrict__ z1f = (const float*)g_z1;
    for (int i = tid; i < 64 * 64; i += 128) {
        int r = i >> 6, c = i & 63;
        int gr = row0 + r;
        float zz = (gr < N_NODES) ? z1f[gr * 64 + c] : 0.f;
        float h = elu(zz * sc[c] + sh[c]);
        ((float*)&hs2[r][0])[c] = h;
    }
    __syncthreads();
    int tx = tid & 7, ty = tid >> 3;
    float acc[4][4];
    #pragma unroll
    for (int i = 0; i < 4; i++)
        #pragma unroll
        for (int j = 0; j < 4; j++) acc[i][j] = 0.f;
    for (int kk = 0; kk < 32; kk++) {
        float4 w0 = ws4[2 * kk][tx];
        float4 w1 = ws4[2 * kk + 1][tx];
        #pragma unroll
        for (int i = 0; i < 4; i++) {
            float2 xv = hs2[ty + 16 * i][kk];
            acc[i][0] = fmaf(xv.x, w0.x, fmaf(xv.y, w1.x, acc[i][0]));
            acc[i][1] = fmaf(xv.x, w0.y, fmaf(xv.y, w1.y, acc[i][1]));
            acc[i][2] = fmaf(xv.x, w0.z, fmaf(xv.y, w1.z, acc[i][2]));
            acc[i][3] = fmaf(xv.x, w0.w, fmaf(xv.y, w1.w, acc[i][3]));
        }
    }
    #pragma unroll
    for (int i = 0; i < 4; i++) {
        int r = row0 + ty + 16 * i;
        if (r < N_NODES) {
            float d = g_dinv[r];
            g_y2[r * 8 + tx] = make_float4(acc[i][0] * d, acc[i][1] * d,
                                           acc[i][2] * d, acc[i][3] * d);
        }
    }
}

// layer-2 aggregation: TWO nodes/warp, 16 lanes x float2 (2ch each)
__global__ void __launch_bounds__(256, 6) k_agg32() {
    __shared__ float bs[32], bq[32];
    int tid = threadIdx.x;
    if (tid < 32) { bs[tid] = 0.f; bq[tid] = 0.f; }
    __syncthreads();
    int lane = tid & 31;
    int half = lane >> 4, hl = lane & 15;
    int warp = blockIdx.x * 8 + (tid >> 5);
    int nwarps = gridDim.x * 8;
    const float2* __restrict__ y = (const float2*)g_y2;
    float2* __restrict__ z = (float2*)g_z2;
    float ls0 = 0.f, lq0 = 0.f, ls1 = 0.f, lq1 = 0.f;
    for (int p = warp; p < N_NODES / 2; p += nwarps) {
        int n = 2 * p + half;
        int start = g_rowptr[n], end = g_rowptr[n + 1];
        int c = end - start;
        float dn = g_dinv[n];
        float2 a = y[n * 16 + hl];                       // self (pre-scaled)
        int cpeer = __shfl_xor_sync(0xffffffffu, c, 16); // convergent
        int cm = c > cpeer ? c : cpeer;
        for (int base = 0; base < cm; base += 16) {
            int m = c - base;
            if (m < 0) m = 0;
            if (m > 16) m = 16;
            int mm = cm - base;
            if (mm > 16) mm = 16;
            int s = (hl < m) ? g_col[start + base + hl] : 0;
            for (int j = 0; j < mm; j++) {
                int sj = __shfl_sync(0xffffffffu, s, j, 16);
                if (j < m) {
                    float2 v = y[sj * 16 + hl];
                    a.x += v.x; a.y += v.y;
                }
            }
        }
        a.x *= dn; a.y *= dn;
        z[n * 16 + hl] = a;
        ls0 += a.x; lq0 += a.x * a.x;
        ls1 += a.y; lq1 += a.y * a.y;
    }
    atomicAdd(&bs[2 * hl], ls0);     atomicAdd(&bq[2 * hl], lq0);
    atomicAdd(&bs[2 * hl + 1], ls1); atomicAdd(&bq[2 * hl + 1], lq1);
    __syncthreads();
    if (tid < 32) { atomicAdd(&g_bns[64 + tid], bs[tid]); atomicAdd(&g_bnq[64 + tid], bq[tid]); }
}

// ---------------- pooling + head ----------------
__global__ void k_pool(const int* __restrict__ batch,
                       const float* __restrict__ g2, const float* __restrict__ be2) {
    int lane = threadIdx.x & 31;
    int warp = blockIdx.x * (blockDim.x >> 5) + (threadIdx.x >> 5);
    int n0 = warp * 32;
    if (n0 >= N_NODES) return;
    int n1 = n0 + 32;
    if (n1 > N_NODES) n1 = N_NODES;
    const float* __restrict__ z = (const float*)g_z2;
    float m = g_bns[64 + lane] * (1.0f / N_NODES);
    float var = g_bnq[64 + lane] * (1.0f / N_NODES) - m * m;
    float r = rsqrtf(var + 1e-5f);
    float sc = g2[lane] * r;
    float sh = be2[lane] - m * sc;
    int cur = -1;
    float s = 0.f, mx = -3.0e38f;
    int cnt = 0;
    for (int n = n0; n < n1; n++) {
        int g = batch[n];
        float zz = z[n * 32 + lane];
        float h = elu(zz * sc + sh);
        if (g != cur) {
            if (cnt > 0) {
                atomicAdd(&g_psum[cur * 32 + lane], s);
                atomicMax(&g_pmax[cur * 32 + lane], encf(mx));
                if (lane == 0) atomicAdd(&g_cnt[cur], (float)cnt);
            }
            cur = g; s = 0.f; mx = -3.0e38f; cnt = 0;
        }
        s += h;
        mx = fmaxf(mx, h);
        cnt++;
    }
    if (cnt > 0) {
        atomicAdd(&g_psum[cur * 32 + lane], s);
        atomicMax(&g_pmax[cur * 32 + lane], encf(mx));
        if (lane == 0) atomicAdd(&g_cnt[cur], (float)cnt);
    }
}

// final MLP head; self-cleans accumulator state
__global__ void k_mlp(const float* __restrict__ Wm1, const float* __restrict__ bm1,
                      const float* __restrict__ Wm2, const float* __restrict__ bm2,
                      float* __restrict__ out) {
    __shared__ float gv[64], hid[32];
    int g = blockIdx.x, t = threadIdx.x;   // 32 threads
    float c = g_cnt[g];
    float cm = fmaxf(c, 1.f);
    gv[t] = g_psum[g * 32 + t] / cm;
    gv[32 + t] = (c > 0.f) ? decf(g_pmax[g * 32 + t]) : 0.f;
    __syncwarp();
    g_psum[g * 32 + t] = 0.f;
    g_pmax[g * 32 + t] = 0u;
    if (t == 0) g_cnt[g] = 0.f;
    if (g == 0) {
        g_bns[t] = 0.f; g_bns[t + 32] = 0.f; g_bns[t + 64] = 0.f;
        g_bnq[t] = 0.f; g_bnq[t + 32] = 0.f; g_bnq[t + 64] = 0.f;
    }
    float acc = bm1[t];
    #pragma unroll
    for (int k = 0; k < 64; k++) acc += gv[k] * Wm1[k * 32 + t];
    hid[t] = elu(acc);
    __syncwarp();
    if (t < 2) {
        float o = bm2[t];
        #pragma unroll
        for (int k = 0; k < 32; k++) o += hid[k] * Wm2[k * 2 + t];
        out[g * 2 + t] = o;
    }
}

// ---------------- launch ----------------
static cudaStream_t s_side = 0;
static cudaEvent_t  ev_dinv = 0, ev_join = 0;

extern "C" void kernel_launch(void* const* d_in, const int* in_sizes, int n_in,
                              void* d_out, int out_size) {
    const float* x     = (const float*)d_in[0];
    const int*   ei    = (const int*)d_in[1];     // int32 (JAX x64 disabled)
    const int*   batch = (const int*)d_in[3];     // int32
    const float* W1    = (const float*)d_in[4];
    const float* g1    = (const float*)d_in[6];
    const float* be1   = (const float*)d_in[7];
    const float* W2    = (const float*)d_in[8];
    const float* g2    = (const float*)d_in[10];
    const float* be2   = (const float*)d_in[11];
    const float* Wm1   = (const float*)d_in[12];
    const float* bm1   = (const float*)d_in[13];
    const float* Wm2   = (const float*)d_in[14];
    const float* bm2   = (const float*)d_in[15];
    float* out = (float*)d_out;

    if (!s_side) {
        cudaStreamCreateWithFlags(&s_side, cudaStreamNonBlocking);
        cudaEventCreateWithFlags(&ev_dinv, cudaEventDisableTiming);
        cudaEventCreateWithFlags(&ev_join, cudaEventDisableTiming);
    }

    // main stream: CSR build
    k_deg<<<6250, 256>>>(ei);
    k_scanA<<<391, 256>>>();
    k_scanC<<<391, 256>>>();
    cudaEventRecord(ev_dinv, 0);              // dinv ready
    cudaStreamWaitEvent(s_side, ev_dinv, 0);
    k_gemm1<<<1563, 256, 0, s_side>>>(x, W1); // overlaps k_fill
    cudaEventRecord(ev_join, s_side);
    k_fill<<<6250, 256>>>(ei);
    cudaStreamWaitEvent(0, ev_join, 0);

    k_agg64<<<888, 256>>>();
    k_gemm2<<<1563, 128>>>(W2, g1, be1);
    k_agg32<<<888, 256>>>();
    k_pool<<<391, 256>>>(batch, g2, be2);
    k_mlp<<<512, 32>>>(Wm1, bm1, Wm2, bm2, out);
}

// round 14
// speedup vs baseline: 1.1005x; 1.1005x over previous
#include <cuda_runtime.h>
#include <cuda_fp16.h>
#include <math.h>

#define N_NODES 100000
#define N_EDGES 1600000
#define N_GRAPHS 512

// ---------------- device scratch (no cudaMalloc allowed) ----------------
__device__ __align__(256) __half2 g_y1h[N_NODES * 32];  // 64 ch fp16, PRE-SCALED by dinv[src]
__device__ __align__(256) float4  g_z1[N_NODES * 16];   // scratch: raw xw fp32, then z1 fp32
__device__ __align__(256) __half2 g_y2h[N_NODES * 16];  // 32 ch fp16, pre-scaled
__device__ __align__(256) float4  g_z2[N_NODES * 8];    // 32 ch fp32
__device__ int      g_indeg[N_NODES];     // reset by k_scanC
__device__ int      g_rowptr[N_NODES + 1];
__device__ int      g_cursor[N_NODES];
__device__ int      g_col[N_EDGES];
__device__ float    g_dinv[N_NODES];
__device__ float    g_bns[96];            // reset by k_mlp
__device__ float    g_bnq[96];            // reset by k_mlp
__device__ float    g_psum[N_GRAPHS * 32];   // reset by k_mlp
__device__ unsigned g_pmax[N_GRAPHS * 32];   // reset by k_mlp
__device__ float    g_cnt[N_GRAPHS];         // reset by k_mlp
__device__ int      g_bsums[512];

__device__ __forceinline__ float elu(float x) {
    return x > 0.f ? x : (__expf(x) - 1.f);
}
__device__ __forceinline__ unsigned encf(float f) {
    unsigned u = __float_as_uint(f);
    return (u & 0x80000000u) ? ~u : (u | 0x80000000u);
}
__device__ __forceinline__ float decf(unsigned u) {
    return (u & 0x80000000u) ? __uint_as_float(u ^ 0x80000000u)
                             : __uint_as_float(~u);
}

// ---------------- CSR build ----------------
__global__ void k_deg(const int* __restrict__ ei) {
    int e = blockIdx.x * blockDim.x + threadIdx.x;
    if (e < N_EDGES) atomicAdd(&g_indeg[ei[N_EDGES + e]], 1);
}

__global__ void k_scanA() {
    __shared__ int wsum[8];
    int tid = threadIdx.x, lane = tid & 31, w = tid >> 5;
    int i = blockIdx.x * 256 + tid;
    int v = (i < N_NODES) ? g_indeg[i] : 0;
    int sc = v;
    #pragma unroll
    for (int o = 1; o < 32; o <<= 1) {
        int t = __shfl_up_sync(0xffffffffu, sc, o);
        if (lane >= o) sc += t;
    }
    if (lane == 31) wsum[w] = sc;
    __syncthreads();
    if (w == 0) {
        int ws = (lane < 8) ? wsum[lane] : 0;
        #pragma unroll
        for (int o = 1; o < 8; o <<= 1) {
            int t = __shfl_up_sync(0xffffffffu, ws, o);
            if (lane >= o) ws += t;
        }
        if (lane < 8) wsum[lane] = ws;
    }
    __syncthreads();
    int inc = sc + ((w > 0) ? wsum[w - 1] : 0);
    if (i < N_NODES) g_rowptr[i + 1] = inc;
    if (tid == 255) g_bsums[blockIdx.x] = inc;
}

__global__ void k_scanC() {
    __shared__ int red[8];
    __shared__ int s_off;
    int tid = threadIdx.x, lane = tid & 31, w = tid >> 5;
    int acc = 0;
    for (int t = tid; t < (int)blockIdx.x; t += 256) acc += g_bsums[t];
    #pragma unroll
    for (int o = 16; o; o >>= 1) acc += __shfl_down_sync(0xffffffffu, acc, o);
    if (lane == 0) red[w] = acc;
    __syncthreads();
    if (tid == 0) {
        int s = 0;
        #pragma unroll
        for (int k = 0; k < 8; k++) s += red[k];
        s_off = s;
    }
    __syncthreads();
    int i = blockIdx.x * 256 + tid;
    if (i < N_NODES) {
        int inc = g_rowptr[i + 1] + s_off;
        g_rowptr[i + 1] = inc;
        int dg = g_indeg[i];
        g_indeg[i] = 0;                       // self-clean
        g_cursor[i] = inc - dg;
        g_dinv[i] = rsqrtf((float)dg + 1.0f);
        if (i == 0) g_rowptr[0] = 0;
    }
}

__global__ void k_fill(const int* __restrict__ ei) {
    int e = blockIdx.x * blockDim.x + threadIdx.x;
    if (e < N_EDGES) {
        int s = ei[e];
        int d = ei[N_EDGES + e];
        int p = atomicAdd(&g_cursor[d], 1);
        g_col[p] = s;
    }
}

// ---------------- layer 1 ----------------
// xw = x @ W1 (raw fp32, into g_z1 scratch). NO dinv dependency -> side stream t=0.
__global__ void k_gemm1(const float* __restrict__ x, const float* __restrict__ W1) {
    __shared__ float2 xs2[64][33];   // row stride 66 words == 2 mod 32, conflict-free
    __shared__ float4 ws4[66][16];
    int tid = threadIdx.x;
    int row0 = blockIdx.x * 64;
    const float4* __restrict__ W14 = (const float4*)W1;
    for (int i = tid; i < 66 * 16; i += 256) ws4[i >> 4][i & 15] = W14[i];
    for (int i = tid; i < 64 * 33; i += 256) {
        int r = i / 33, kk = i - r * 33;
        int gr = row0 + r;
        float a = 0.f, b = 0.f;
        if (gr < N_NODES) {
            a = x[gr * 66 + 2 * kk];
            b = x[gr * 66 + 2 * kk + 1];
        }
        xs2[r][kk] = make_float2(a, b);
    }
    __syncthreads();
    int tx = tid & 15, ty = tid >> 4;
    float acc[4][4];
    #pragma unroll
    for (int i = 0; i < 4; i++)
        #pragma unroll
        for (int j = 0; j < 4; j++) acc[i][j] = 0.f;
    for (int kk = 0; kk < 33; kk++) {
        float4 w0 = ws4[2 * kk][tx];
        float4 w1 = ws4[2 * kk + 1][tx];
        #pragma unroll
        for (int i = 0; i < 4; i++) {
            float2 xv = xs2[ty + 16 * i][kk];
            acc[i][0] = fmaf(xv.x, w0.x, fmaf(xv.y, w1.x, acc[i][0]));
            acc[i][1] = fmaf(xv.x, w0.y, fmaf(xv.y, w1.y, acc[i][1]));
            acc[i][2] = fmaf(xv.x, w0.z, fmaf(xv.y, w1.z, acc[i][2]));
            acc[i][3] = fmaf(xv.x, w0.w, fmaf(xv.y, w1.w, acc[i][3]));
        }
    }
    #pragma unroll
    for (int i = 0; i < 4; i++) {
        int r = row0 + ty + 16 * i;
        if (r < N_NODES)
            g_z1[r * 16 + tx] = make_float4(acc[i][0], acc[i][1], acc[i][2], acc[i][3]);
    }
}

// y1h = xw * dinv (fp16). Side stream after dinv ready; hidden under k_fill.
__global__ void k_scale() {
    int i = blockIdx.x * blockDim.x + threadIdx.x;   // over N_NODES*16 float4s
    if (i < N_NODES * 16) {
        float4 v = g_z1[i];
        float d = g_dinv[i >> 4];
        g_y1h[2 * i]     = __floats2half2_rn(v.x * d, v.y * d);
        g_y1h[2 * i + 1] = __floats2half2_rn(v.z * d, v.w * d);
    }
}

// z1[n] = dinv[n]*( y1[n] + sum_s y1[s] ), y1 pre-scaled fp16; fused BN stats (R12 version)
__global__ void __launch_bounds__(256, 6) k_agg64() {
    __shared__ float bs[64], bq[64];
    int tid = threadIdx.x;
    if (tid < 64) { bs[tid] = 0.f; bq[tid] = 0.f; }
    __syncthreads();
    int lane = tid & 31;
    int warp = blockIdx.x * 8 + (tid >> 5);
    int nwarps = gridDim.x * 8;
    const __half2* __restrict__ y = g_y1h;
    float2* __restrict__ z = (float2*)g_z1;
    float ls0 = 0.f, lq0 = 0.f, ls1 = 0.f, lq1 = 0.f;
    for (int n = warp; n < N_NODES; n += nwarps) {
        int start = g_rowptr[n], end = g_rowptr[n + 1];
        float dn = g_dinv[n];
        float2 a = __half22float2(y[n * 32 + lane]);   // self term (pre-scaled)
        for (int base = start; base < end; base += 32) {
            int m = end - base;
            if (m > 32) m = 32;
            int s = (lane < m) ? g_col[base + lane] : 0;
            int j = 0;
            for (; j + 3 < m; j += 4) {
                int s0 = __shfl_sync(0xffffffffu, s, j);
                int s1 = __shfl_sync(0xffffffffu, s, j + 1);
                int s2 = __shfl_sync(0xffffffffu, s, j + 2);
                int s3 = __shfl_sync(0xffffffffu, s, j + 3);
                float2 v0 = __half22float2(y[s0 * 32 + lane]);
                float2 v1 = __half22float2(y[s1 * 32 + lane]);
                float2 v2 = __half22float2(y[s2 * 32 + lane]);
                float2 v3 = __half22float2(y[s3 * 32 + lane]);
                a.x += v0.x + v1.x + v2.x + v3.x;
                a.y += v0.y + v1.y + v2.y + v3.y;
            }
            for (; j < m; j++) {
                int s0 = __shfl_sync(0xffffffffu, s, j);
                float2 v0 = __half22float2(y[s0 * 32 + lane]);
                a.x += v0.x; a.y += v0.y;
            }
        }
        a.x *= dn; a.y *= dn;
        z[n * 32 + lane] = a;
        ls0 += a.x; lq0 += a.x * a.x;
        ls1 += a.y; lq1 += a.y * a.y;
    }
    atomicAdd(&bs[2 * lane], ls0);     atomicAdd(&bq[2 * lane], lq0);
    atomicAdd(&bs[2 * lane + 1], ls1); atomicAdd(&bq[2 * lane + 1], lq1);
    __syncthreads();
    if (tid < 64) { atomicAdd(&g_bns[tid], bs[tid]); atomicAdd(&g_bnq[tid], bq[tid]); }
}

// ---------------- layer 2 ----------------
// h1 = elu(BN(z1)); y2h = (h1 @ W2) * dinv (fp16). k-vectorized smem.
__global__ void k_gemm2(const float* __restrict__ W2,
                        const float* __restrict__ g1, const float* __restrict__ be1) {
    __shared__ float2 hs2[64][33];   // stride 66 words == 2 mod 32
    __shared__ float4 ws4[64][8];
    __shared__ float  sc[64], sh[64];
    int tid = threadIdx.x;          // 128 threads
    int row0 = blockIdx.x * 64;
    if (tid < 64) {
        float m = g_bns[tid] * (1.0f / N_NODES);
        float var = g_bnq[tid] * (1.0f / N_NODES) - m * m;
        float r = rsqrtf(var + 1e-5f);
        float s = g1[tid] * r;
        sc[tid] = s;
        sh[tid] = be1[tid] - m * s;
    }
    const float4* __restrict__ W24 = (const float4*)W2;
    for (int i = tid; i < 64 * 8; i += 128) ws4[i >> 3][i & 7] = W24[i];
    __syncthreads();
    const float* __restrict__ z1f = (const float*)g_z1;
    for (int i = tid; i < 64 * 64; i += 128) {
        int r = i >> 6, c = i & 63;
        int gr = row0 + r;
        float zz = (gr < N_NODES) ? z1f[gr * 64 + c] : 0.f;
        float h = elu(zz * sc[c] + sh[c]);
        ((float*)&hs2[r][0])[c] = h;
    }
    __syncthreads();
    int tx = tid & 7, ty = tid >> 3;
    float acc[4][4];
    #pragma unroll
    for (int i = 0; i < 4; i++)
        #pragma unroll
        for (int j = 0; j < 4; j++) acc[i][j] = 0.f;
    for (int kk = 0; kk < 32; kk++) {
        float4 w0 = ws4[2 * kk][tx];
        float4 w1 = ws4[2 * kk + 1][tx];
        #pragma unroll
        for (int i = 0; i < 4; i++) {
            float2 xv = hs2[ty + 16 * i][kk];
            acc[i][0] = fmaf(xv.x, w0.x, fmaf(xv.y, w1.x, acc[i][0]));
            acc[i][1] = fmaf(xv.x, w0.y, fmaf(xv.y, w1.y, acc[i][1]));
            acc[i][2] = fmaf(xv.x, w0.z, fmaf(xv.y, w1.z, acc[i][2]));
            acc[i][3] = fmaf(xv.x, w0.w, fmaf(xv.y, w1.w, acc[i][3]));
        }
    }
    #pragma unroll
    for (int i = 0; i < 4; i++) {
        int r = row0 + ty + 16 * i;
        if (r < N_NODES) {
            float d = g_dinv[r];
            g_y2h[r * 16 + 2 * tx]     = __floats2half2_rn(acc[i][0] * d, acc[i][1] * d);
            g_y2h[r * 16 + 2 * tx + 1] = __floats2half2_rn(acc[i][2] * d, acc[i][3] * d);
        }
    }
}

// layer-2 aggregation: TWO nodes per warp (16-lane halves, half2 payload) (R12 version)
__global__ void __launch_bounds__(256, 6) k_agg32() {
    __shared__ float bs[32], bq[32];
    int tid = threadIdx.x;
    if (tid < 32) { bs[tid] = 0.f; bq[tid] = 0.f; }
    __syncthreads();
    int lane = tid & 31;
    int half = lane >> 4, hl = lane & 15;
    int warp = blockIdx.x * 8 + (tid >> 5);
    int nwarps = gridDim.x * 8;
    const __half2* __restrict__ y = g_y2h;
    float2* __restrict__ z = (float2*)g_z2;
    float ls0 = 0.f, lq0 = 0.f, ls1 = 0.f, lq1 = 0.f;
    for (int p = warp; p < N_NODES / 2; p += nwarps) {
        int n = 2 * p + half;
        int start = g_rowptr[n], end = g_rowptr[n + 1];
        int c = end - start;
        float dn = g_dinv[n];
        float2 a = __half22float2(y[n * 16 + hl]);       // self (pre-scaled)
        int cpeer = __shfl_xor_sync(0xffffffffu, c, 16); // convergent
        int cm = c > cpeer ? c : cpeer;
        for (int base = 0; base < cm; base += 16) {
            int m = c - base;
            if (m < 0) m = 0;
            if (m > 16) m = 16;
            int mm = cm - base;
            if (mm > 16) mm = 16;
            int s = (hl < m) ? g_col[start + base + hl] : 0;
            for (int j = 0; j < mm; j++) {
                int sj = __shfl_sync(0xffffffffu, s, j, 16);
                if (j < m) {
                    float2 v = __half22float2(y[sj * 16 + hl]);
                    a.x += v.x; a.y += v.y;
                }
            }
        }
        a.x *= dn; a.y *= dn;
        z[n * 16 + hl] = a;
        ls0 += a.x; lq0 += a.x * a.x;
        ls1 += a.y; lq1 += a.y * a.y;
    }
    atomicAdd(&bs[2 * hl], ls0);     atomicAdd(&bq[2 * hl], lq0);
    atomicAdd(&bs[2 * hl + 1], ls1); atomicAdd(&bq[2 * hl + 1], lq1);
    __syncthreads();
    if (tid < 32) { atomicAdd(&g_bns[64 + tid], bs[tid]); atomicAdd(&g_bnq[64 + tid], bq[tid]); }
}

// ---------------- pooling + head ----------------
__global__ void k_pool(const int* __restrict__ batch,
                       const float* __restrict__ g2, const float* __restrict__ be2) {
    int lane = threadIdx.x & 31;
    int warp = blockIdx.x * (blockDim.x >> 5) + (threadIdx.x >> 5);
    int n0 = warp * 32;
    if (n0 >= N_NODES) return;
    int n1 = n0 + 32;
    if (n1 > N_NODES) n1 = N_NODES;
    const float* __restrict__ z = (const float*)g_z2;
    float m = g_bns[64 + lane] * (1.0f / N_NODES);
    float var = g_bnq[64 + lane] * (1.0f / N_NODES) - m * m;
    float r = rsqrtf(var + 1e-5f);
    float sc = g2[lane] * r;
    float sh = be2[lane] - m * sc;
    int cur = -1;
    float s = 0.f, mx = -3.0e38f;
    int cnt = 0;
    for (int n = n0; n < n1; n++) {
        int g = batch[n];
        float zz = z[n * 32 + lane];
        float h = elu(zz * sc + sh);
        if (g != cur) {
            if (cnt > 0) {
                atomicAdd(&g_psum[cur * 32 + lane], s);
                atomicMax(&g_pmax[cur * 32 + lane], encf(mx));
                if (lane == 0) atomicAdd(&g_cnt[cur], (float)cnt);
            }
            cur = g; s = 0.f; mx = -3.0e38f; cnt = 0;
        }
        s += h;
        mx = fmaxf(mx, h);
        cnt++;
    }
    if (cnt > 0) {
        atomicAdd(&g_psum[cur * 32 + lane], s);
        atomicMax(&g_pmax[cur * 32 + lane], encf(mx));
        if (lane == 0) atomicAdd(&g_cnt[cur], (float)cnt);
    }
}

// final MLP head; self-cleans accumulator state
__global__ void k_mlp(const float* __restrict__ Wm1, const float* __restrict__ bm1,
                      const float* __restrict__ Wm2, const float* __restrict__ bm2,
                      float* __restrict__ out) {
    __shared__ float gv[64], hid[32];
    int g = blockIdx.x, t = threadIdx.x;   // 32 threads
    float c = g_cnt[g];
    float cm = fmaxf(c, 1.f);
    gv[t] = g_psum[g * 32 + t] / cm;
    gv[32 + t] = (c > 0.f) ? decf(g_pmax[g * 32 + t]) : 0.f;
    __syncwarp();
    g_psum[g * 32 + t] = 0.f;
    g_pmax[g * 32 + t] = 0u;
    if (t == 0) g_cnt[g] = 0.f;
    if (g == 0) {
        g_bns[t] = 0.f; g_bns[t + 32] = 0.f; g_bns[t + 64] = 0.f;
        g_bnq[t] = 0.f; g_bnq[t + 32] = 0.f; g_bnq[t + 64] = 0.f;
    }
    float acc = bm1[t];
    #pragma unroll
    for (int k = 0; k < 64; k++) acc += gv[k] * Wm1[k * 32 + t];
    hid[t] = elu(acc);
    __syncwarp();
    if (t < 2) {
        float o = bm2[t];
        #pragma unroll
        for (int k = 0; k < 32; k++) o += hid[k] * Wm2[k * 2 + t];
        out[g * 2 + t] = o;
    }
}

// ---------------- launch ----------------
static cudaStream_t s_side = 0;
static cudaEvent_t  ev_fork = 0, ev_dinv = 0, ev_join = 0;

extern "C" void kernel_launch(void* const* d_in, const int* in_sizes, int n_in,
                              void* d_out, int out_size) {
    const float* x     = (const float*)d_in[0];
    const int*   ei    = (const int*)d_in[1];     // int32 (JAX x64 disabled)
    const int*   batch = (const int*)d_in[3];     // int32
    const float* W1    = (const float*)d_in[4];
    const float* g1    = (const float*)d_in[6];
    const float* be1   = (const float*)d_in[7];
    const float* W2    = (const float*)d_in[8];
    const float* g2    = (const float*)d_in[10];
    const float* be2   = (const float*)d_in[11];
    const float* Wm1   = (const float*)d_in[12];
    const float* bm1   = (const float*)d_in[13];
    const float* Wm2   = (const float*)d_in[14];
    const float* bm2   = (const float*)d_in[15];
    float* out = (float*)d_out;

    if (!s_side) {
        cudaStreamCreateWithFlags(&s_side, cudaStreamNonBlocking);
        cudaEventCreateWithFlags(&ev_fork, cudaEventDisableTiming);
        cudaEventCreateWithFlags(&ev_dinv, cudaEventDisableTiming);
        cudaEventCreateWithFlags(&ev_join, cudaEventDisableTiming);
    }

    // fork at t=0: gemm1 (raw xw, no dinv needed) runs under the CSR build
    cudaEventRecord(ev_fork, 0);
    cudaStreamWaitEvent(s_side, ev_fork, 0);
    k_gemm1<<<1563, 256, 0, s_side>>>(x, W1);

    // main stream: CSR build
    k_deg<<<6250, 256>>>(ei);
    k_scanA<<<391, 256>>>();
    k_scanC<<<391, 256>>>();
    cudaEventRecord(ev_dinv, 0);               // dinv ready
    cudaStreamWaitEvent(s_side, ev_dinv, 0);
    k_scale<<<6250, 256, 0, s_side>>>();       // y1h = xw*dinv, hidden under fill
    cudaEventRecord(ev_join, s_side);
    k_fill<<<6250, 256>>>(ei);
    cudaStreamWaitEvent(0, ev_join, 0);

    k_agg64<<<888, 256>>>();
    k_gemm2<<<1563, 128>>>(W2, g1, be1);
    k_agg32<<<888, 256>>>();
    k_pool<<<391, 256>>>(batch, g2, be2);
    k_mlp<<<512, 32>>>(Wm1, bm1, Wm2, bm2, out);
}